// round 1
// baseline (speedup 1.0000x reference)
#include <cuda_runtime.h>
#include <cuda_bf16.h>

// Elementwise fused: out = (x + 2) + (x * 3) - (x - 1) * (x * 0.5)
// 8192 x 16384 fp32 = 134217728 elements, divisible by 4 -> pure float4 path.

__global__ void fused_elemwise_kernel(const float4* __restrict__ x,
                                      float4* __restrict__ out,
                                      int n4) {
    int i = blockIdx.x * blockDim.x + threadIdx.x;
    if (i < n4) {
        float4 v = x[i];
        float4 r;
        r.x = (v.x + 2.0f) + (v.x * 3.0f) - (v.x - 1.0f) * (v.x * 0.5f);
        r.y = (v.y + 2.0f) + (v.y * 3.0f) - (v.y - 1.0f) * (v.y * 0.5f);
        r.z = (v.z + 2.0f) + (v.z * 3.0f) - (v.z - 1.0f) * (v.z * 0.5f);
        r.w = (v.w + 2.0f) + (v.w * 3.0f) - (v.w - 1.0f) * (v.w * 0.5f);
        out[i] = r;
    }
}

// Tail handler for non-multiple-of-4 counts (not expected here, but safe).
__global__ void fused_elemwise_tail(const float* __restrict__ x,
                                    float* __restrict__ out,
                                    int start, int n) {
    int i = start + blockIdx.x * blockDim.x + threadIdx.x;
    if (i < n) {
        float v = x[i];
        out[i] = (v + 2.0f) + (v * 3.0f) - (v - 1.0f) * (v * 0.5f);
    }
}

extern "C" void kernel_launch(void* const* d_in, const int* in_sizes, int n_in,
                              void* d_out, int out_size) {
    const float* x = (const float*)d_in[0];
    float* out = (float*)d_out;
    int n = in_sizes[0];

    int n4 = n / 4;
    if (n4 > 0) {
        int threads = 256;
        int blocks = (n4 + threads - 1) / threads;
        fused_elemwise_kernel<<<blocks, threads>>>((const float4*)x,
                                                   (float4*)out, n4);
    }
    int rem = n - n4 * 4;
    if (rem > 0) {
        fused_elemwise_tail<<<1, 256>>>(x, out, n4 * 4, n);
    }
}

// round 2
// speedup vs baseline: 1.0110x; 1.0110x over previous
#include <cuda_runtime.h>
#include <cuda_bf16.h>

// Elementwise fused: out = (x + 2) + (x * 3) - (x - 1) * (x * 0.5)
// 8192 x 16384 fp32 = 134217728 elements = 33554432 float4s.
// Pure streaming: batch 4 float4 loads per thread (MLP=4), evict-first hints.

__device__ __forceinline__ float fuse1(float v) {
    return (v + 2.0f) + (v * 3.0f) - (v - 1.0f) * (v * 0.5f);
}

__device__ __forceinline__ float4 fuse4(float4 v) {
    float4 r;
    r.x = fuse1(v.x);
    r.y = fuse1(v.y);
    r.z = fuse1(v.z);
    r.w = fuse1(v.w);
    return r;
}

template <int UNROLL>
__global__ void fused_elemwise_kernel(const float4* __restrict__ x,
                                      float4* __restrict__ out,
                                      int n4) {
    int stride = gridDim.x * blockDim.x;
    int base = blockIdx.x * blockDim.x + threadIdx.x;

    // Fast path: all UNROLL indices in range (true for every thread when the
    // grid exactly tiles n4).
    int last = base + (UNROLL - 1) * stride;
    if (last < n4) {
        float4 v[UNROLL];
#pragma unroll
        for (int k = 0; k < UNROLL; k++)
            v[k] = __ldcs(&x[base + k * stride]);   // front-batched loads, MLP=UNROLL
#pragma unroll
        for (int k = 0; k < UNROLL; k++)
            __stcs(&out[base + k * stride], fuse4(v[k]));
    } else {
        for (int i = base; i < n4; i += stride)
            __stcs(&out[i], fuse4(__ldcs(&x[i])));
    }
}

__global__ void fused_elemwise_tail(const float* __restrict__ x,
                                    float* __restrict__ out,
                                    int start, int n) {
    int i = start + blockIdx.x * blockDim.x + threadIdx.x;
    if (i < n) out[i] = fuse1(x[i]);
}

extern "C" void kernel_launch(void* const* d_in, const int* in_sizes, int n_in,
                              void* d_out, int out_size) {
    const float* x = (const float*)d_in[0];
    float* out = (float*)d_out;
    int n = in_sizes[0];

    int n4 = n / 4;
    if (n4 > 0) {
        constexpr int UNROLL = 4;
        const int threads = 256;
        int total_threads = (n4 + UNROLL - 1) / UNROLL;
        int blocks = (total_threads + threads - 1) / threads;
        fused_elemwise_kernel<UNROLL><<<blocks, threads>>>(
            (const float4*)x, (float4*)out, n4);
    }
    int rem = n - n4 * 4;
    if (rem > 0) {
        fused_elemwise_tail<<<1, 256>>>(x, out, n4 * 4, n);
    }
}